// round 9
// baseline (speedup 1.0000x reference)
#include <cuda_runtime.h>
#include <float.h>

// Chamfer distance, B=4, N=M=4096, D=3.
// dst-split 32x (128 pts, 2KB smem), S=4 src/thread, packed fma.rn.f32x2
// (2 dst per op; FFMA2 is rt4 on sm_103a -> same FLOPs as scalar, fewer
// issue slots). Split partial mins combined with atomicMax on the monotone
// key = 0x7F7FFFFF - float_bits(dist) (dist clamped >= 0): zero-initialized
// __device__ array is the identity -> no init kernel. Finalize CTA decodes,
// sums fixed-order, resets slots for the next graph replay. Deterministic.

#define BATCH 4
#define NPTS  4096
#define TPB   256
#define SRC_PER_THREAD 4
#define SRC_PER_CTA (TPB * SRC_PER_THREAD)       // 1024
#define CHUNKS (NPTS / SRC_PER_CTA)              // 4
#define NSPLIT 32
#define SPLIT_PTS (NPTS / NSPLIT)                // 128
#define SPLIT_PAIRS (SPLIT_PTS / 2)              // 64
#define NSLOTS (2 * BATCH * NPTS)                // 32768
#define NCTAS (CHUNKS * BATCH * 2 * NSPLIT)      // 1024

__device__ unsigned int g_maxkey[NSLOTS];        // 0 == key(FLT_MAX): identity
__device__ unsigned int g_count = 0;

typedef unsigned long long u64;

__device__ __forceinline__ u64 pk(float a, float b) {
    u64 r;
    asm("mov.b64 %0, {%1, %2};" : "=l"(r) : "f"(a), "f"(b));
    return r;
}
__device__ __forceinline__ void upk(u64 v, float& lo, float& hi) {
    asm("mov.b64 {%0, %1}, %2;" : "=f"(lo), "=f"(hi) : "l"(v));
}
__device__ __forceinline__ u64 fma2(u64 a, u64 b, u64 c) {
    u64 d;
    asm("fma.rn.f32x2 %0, %1, %2, %3;" : "=l"(d) : "l"(a), "l"(b), "l"(c));
    return d;
}

__global__ void __launch_bounds__(TPB) chamfer_kernel(
    const float* __restrict__ recon,
    const float* __restrict__ gt,
    float* __restrict__ out)
{
    __shared__ ulonglong2 sdst[SPLIT_PTS];   // 2 KB (2 entries per dst pair)

    const int bx    = blockIdx.x;        // src chunk (0..3)
    const int b     = blockIdx.y;        // batch
    const int zz    = blockIdx.z;        // dir*NSPLIT + split
    const int dir   = zz >> 5;
    const int split = zz & 31;
    const int tid   = threadIdx.x;

    const float* src = (dir == 0) ? recon : gt;
    const float* dst = (dir == 0) ? gt : recon;
    const float* dstb = dst + ((size_t)b * NPTS + (size_t)split * SPLIT_PTS) * 3;

    // Prologue: 128 threads pack 64 dst pairs (2 smem entries per pair).
    if (tid < 2 * SPLIT_PAIRS) {
        const int p = tid >> 1;              // pair index
        const int h = tid & 1;               // 0: {xx,yy}  1: {zz,ww}
        const float* g0 = dstb + 6 * p;
        float x0 = g0[0], y0 = g0[1], z0 = g0[2];
        float x1 = g0[3], y1 = g0[4], z1 = g0[5];
        if (h == 0) {
            sdst[2 * p] = make_ulonglong2(pk(x0, x1), pk(y0, y1));
        } else {
            float w0 = fmaf(x0, x0, fmaf(y0, y0, z0 * z0));
            float w1 = fmaf(x1, x1, fmaf(y1, y1, z1 * z1));
            sdst[2 * p + 1] = make_ulonglong2(pk(z0, z1), pk(w0, w1));
        }
    }
    __syncthreads();

    // Four src points per thread; q vectors packed (same value both halves).
    u64 qx[4], qy[4], qz[4];
    float npv[4];
    const size_t base = (size_t)b * NPTS + bx * SRC_PER_CTA + tid;
    #pragma unroll
    for (int k = 0; k < 4; ++k) {
        const float* sp = src + (base + k * TPB) * 3;
        float px = sp[0], py = sp[1], pz = sp[2];
        qx[k] = pk(-2.0f * px, -2.0f * px);
        qy[k] = pk(-2.0f * py, -2.0f * py);
        qz[k] = pk(-2.0f * pz, -2.0f * pz);
        npv[k] = fmaf(px, px, fmaf(py, py, pz * pz));
    }

    float mlo0 = FLT_MAX, mhi0 = FLT_MAX;
    float mlo1 = FLT_MAX, mhi1 = FLT_MAX;
    float mlo2 = FLT_MAX, mhi2 = FLT_MAX;
    float mlo3 = FLT_MAX, mhi3 = FLT_MAX;

    #pragma unroll 8
    for (int j = 0; j < SPLIT_PAIRS; ++j) {
        ulonglong2 A = sdst[2 * j];       // {xx, yy}
        ulonglong2 B = sdst[2 * j + 1];   // {zz, ww}

        u64 d0 = fma2(qx[0], A.x, fma2(qy[0], A.y, fma2(qz[0], B.x, B.y)));
        u64 d1 = fma2(qx[1], A.x, fma2(qy[1], A.y, fma2(qz[1], B.x, B.y)));
        u64 d2 = fma2(qx[2], A.x, fma2(qy[2], A.y, fma2(qz[2], B.x, B.y)));
        u64 d3 = fma2(qx[3], A.x, fma2(qy[3], A.y, fma2(qz[3], B.x, B.y)));

        float lo, hi;
        upk(d0, lo, hi); mlo0 = fminf(mlo0, lo); mhi0 = fminf(mhi0, hi);
        upk(d1, lo, hi); mlo1 = fminf(mlo1, lo); mhi1 = fminf(mhi1, hi);
        upk(d2, lo, hi); mlo2 = fminf(mlo2, lo); mhi2 = fminf(mhi2, hi);
        upk(d3, lo, hi); mlo3 = fminf(mlo3, lo); mhi3 = fminf(mhi3, hi);
    }

    float mn[4];
    mn[0] = fminf(mlo0, mhi0);
    mn[1] = fminf(mlo1, mhi1);
    mn[2] = fminf(mlo2, mhi2);
    mn[3] = fminf(mlo3, mhi3);

    // Combine across splits: atomicMax on monotone-decreasing key.
    // dist >= 0 (clamped) -> bits <= 0x7F7FFFFF -> key in [0, 0x7F7FFFFF].
    const int slot_base = (dir * BATCH + b) * NPTS + bx * SRC_PER_CTA + tid;
    #pragma unroll
    for (int k = 0; k < 4; ++k) {
        float m = fmaxf(mn[k] + npv[k], 0.0f);
        unsigned int key = 0x7F7FFFFFu - __float_as_uint(m);
        atomicMax(&g_maxkey[slot_base + k * TPB], key);
    }

    // Elect last CTA to finalize.
    __shared__ unsigned int s_last;
    __threadfence();
    __syncthreads();
    if (tid == 0) {
        unsigned int old = atomicAdd(&g_count, 1u);
        s_last = (old == NCTAS - 1) ? 1u : 0u;
    }
    __syncthreads();

    if (s_last) {
        __threadfence();   // all atomics visible
        float acc = 0.0f;
        const uint4* mv = (const uint4*)g_maxkey;
        #pragma unroll 4
        for (int s = tid; s < NSLOTS / 4; s += TPB) {
            uint4 v = mv[s];
            acc += __uint_as_float(0x7F7FFFFFu - v.x)
                 + __uint_as_float(0x7F7FFFFFu - v.y)
                 + __uint_as_float(0x7F7FFFFFu - v.z)
                 + __uint_as_float(0x7F7FFFFFu - v.w);
        }
        __shared__ float sred[TPB];
        sred[tid] = acc;
        __syncthreads();

        // Reset slots to the identity (0) for the next graph replay.
        uint4* mw = (uint4*)g_maxkey;
        const uint4 z4 = make_uint4(0u, 0u, 0u, 0u);
        #pragma unroll 4
        for (int s = tid; s < NSLOTS / 4; s += TPB) mw[s] = z4;

        #pragma unroll
        for (int s = TPB / 2; s > 0; s >>= 1) {
            if (tid < s) sred[tid] += sred[tid + s];
            __syncthreads();
        }
        if (tid == 0) {
            out[0] = sred[0] / (float)NSLOTS;   // == (mean1 + mean2) / 2
            g_count = 0;                        // reset for next replay
        }
    }
}

extern "C" void kernel_launch(void* const* d_in, const int* in_sizes, int n_in,
                              void* d_out, int out_size)
{
    const float* recon = (const float*)d_in[0];
    const float* gt    = (const float*)d_in[1];
    float* out = (float*)d_out;

    dim3 grid(CHUNKS, BATCH, 2 * NSPLIT);   // 4 x 4 x 64 = 1024 CTAs
    chamfer_kernel<<<grid, TPB>>>(recon, gt, out);
}